// round 1
// baseline (speedup 1.0000x reference)
#include <cuda_runtime.h>

// Problem constants
#define Stok 16384
#define Mdim 512
#define Edim 16
#define Ddim 256
#define H1d  500
#define H2d  500
#define H3d  1000

// GEMM tiling
#define TM 64
#define TN 64
#define TKs 16
#define NR (2*Stok + Edim*TM)       // 33792 padded assignment rows
#define NT_MAX (2*Stok/TM + Edim)   // 528 tiles max
#define RBLOCKS (Stok/8)            // 2048 router blocks (8 tokens each)

// -------- scratch (device globals; allocation-free per harness rules) --------
__device__ float g_A1[NR*H1d];
__device__ float g_A2[NR*H2d];
__device__ float g_A3[NR*H3d];
__device__ float g_A4[NR*Ddim];
__device__ int   g_row_token[NR];
__device__ int   g_token_rows[2*Stok];
__device__ float g_gate[2*Stok];
__device__ int   g_topk[2*Stok];
__device__ int   g_counts[Edim];
__device__ int   g_cursor[Edim];
__device__ int   g_offsets[Edim];
__device__ int   g_tile_expert[NT_MAX];
__device__ int   g_tile_row0[NT_MAX];
__device__ int   g_n_tiles;
__device__ float g_proxy_partial[RBLOCKS*Edim];

// ---------------------------------------------------------------------------
__global__ void init_kernel() {
    int t = blockIdx.x*blockDim.x + threadIdx.x;
    if (t < Edim) { g_counts[t] = 0; g_cursor[t] = 0; }
    for (int r = t; r < NR; r += gridDim.x*blockDim.x) g_row_token[r] = 0;
}

// Router: logits = x@Wr^T + noise; softmax; top-2; gates; select0; loss stats.
// 8 warps/block, one token per warp. Wr (16x512, 32KB) staged in smem.
__global__ void router_kernel(const float* __restrict__ x,
                              const float* __restrict__ noise,
                              const float* __restrict__ Wr,
                              float* __restrict__ out_sel) {
    __shared__ float sWr[Edim*Mdim];
    __shared__ float sP[8][Edim];
    int tid = threadIdx.x;
    for (int i = tid; i < Edim*Mdim; i += 256) sWr[i] = Wr[i];
    __syncthreads();

    int warp = tid >> 5, lane = tid & 31;
    int s = blockIdx.x*8 + warp;

    float p[Edim];
    #pragma unroll
    for (int e = 0; e < Edim; e++) p[e] = 0.f;
    const float* xr = x + (long)s*Mdim;
    for (int k = lane; k < Mdim; k += 32) {
        float xv = xr[k];
        #pragma unroll
        for (int e = 0; e < Edim; e++) p[e] += xv * sWr[e*Mdim + k];
    }
    #pragma unroll
    for (int e = 0; e < Edim; e++) {
        #pragma unroll
        for (int o = 16; o > 0; o >>= 1) p[e] += __shfl_xor_sync(0xffffffffu, p[e], o);
    }
    // all lanes now hold all 16 logits
    float mx = -1e30f;
    #pragma unroll
    for (int e = 0; e < Edim; e++) { p[e] += noise[(long)s*Edim + e]; mx = fmaxf(mx, p[e]); }
    float sum = 0.f;
    #pragma unroll
    for (int e = 0; e < Edim; e++) { p[e] = __expf(p[e]-mx); sum += p[e]; }
    float inv = 1.f/sum;
    #pragma unroll
    for (int e = 0; e < Edim; e++) p[e] *= inv;

    // top-2 with lowest-index tie-break (matches lax.top_k)
    int e0 = 0; float v0 = p[0];
    #pragma unroll
    for (int e = 1; e < Edim; e++) if (p[e] > v0) { v0 = p[e]; e0 = e; }
    int e1 = -1; float v1 = -1.f;
    #pragma unroll
    for (int e = 0; e < Edim; e++) if (e != e0 && p[e] > v1) { v1 = p[e]; e1 = e; }
    float gs = v0 + v1;

    if (lane == 0) {
        g_topk[2*s]   = e0; g_topk[2*s+1] = e1;
        g_gate[2*s]   = v0/gs; g_gate[2*s+1] = v1/gs;
        atomicAdd(&g_counts[e0], 1);
        atomicAdd(&g_counts[e1], 1);
        #pragma unroll
        for (int e = 0; e < Edim; e++) sP[warp][e] = p[e];
    }
    if (lane < Edim)
        out_sel[(long)s*Edim + lane] = (lane == e0 || lane == e1) ? 1.f : 0.f;
    __syncthreads();
    if (tid < Edim) {
        float acc = 0.f;
        #pragma unroll
        for (int w = 0; w < 8; w++) acc += sP[w][tid];   // deterministic order
        g_proxy_partial[(long)blockIdx.x*Edim + tid] = acc;
    }
}

// Deterministic reduction of proxy partials + balance loss.
__global__ void loss_kernel(float* __restrict__ out_loss) {
    __shared__ float sp[Edim];
    int e = threadIdx.x;
    if (e < Edim) {
        float acc = 0.f;
        for (int b = 0; b < RBLOCKS; b++) acc += g_proxy_partial[(long)b*Edim + e];
        sp[e] = acc;
    }
    __syncthreads();
    if (e == 0) {
        float l = 0.f;
        for (int i = 0; i < Edim; i++) l += sp[i] * (float)g_counts[i];
        // E * sum_e (P_e/S)*(C_e/S)
        out_loss[0] = l * (float)Edim / ((float)Stok * (float)Stok);
        out_loss[1] = 0.f;   // dist_loss
    }
}

__global__ void build_tiles_kernel() {
    int off = 0, nt = 0;
    for (int e = 0; e < Edim; e++) {
        g_offsets[e] = off;
        int c = g_counts[e];
        int ct = (c + TM - 1)/TM;
        for (int t = 0; t < ct; t++) { g_tile_expert[nt] = e; g_tile_row0[nt] = off + t*TM; nt++; }
        off += ct*TM;
    }
    g_n_tiles = nt;
}

__global__ void scatter_kernel() {
    int s = blockIdx.x*blockDim.x + threadIdx.x;
    if (s >= Stok) return;
    #pragma unroll
    for (int k = 0; k < 2; k++) {
        int e = g_topk[2*s+k];
        int pos = atomicAdd(&g_cursor[e], 1);
        int r = g_offsets[e] + pos;
        g_row_token[r] = s;
        g_token_rows[2*s+k] = r;
    }
}

// Grouped GEMM: Y[r,n] = act( X[r,:] @ W[e] + b[e] ), tiles never cross experts.
template<int KD, int ND, bool RELU, bool GATHER>
__global__ void expert_gemm(const float* __restrict__ Xin,
                            const float* __restrict__ W,
                            const float* __restrict__ Bias,
                            float* __restrict__ Y) {
    int tile = blockIdx.x;
    if (tile >= g_n_tiles) return;
    int e    = g_tile_expert[tile];
    int row0 = g_tile_row0[tile];
    int nb   = blockIdx.y * TN;
    const float* We = W + (long)e*KD*ND;
    const float* be = Bias + (long)e*ND;

    __shared__ float As[TKs][TM];
    __shared__ float Bs[TKs][TN];
    __shared__ int   sRow[TM];

    int tid = threadIdx.x;
    int tx = tid & 15, ty = tid >> 4;

    if (GATHER) {
        if (tid < TM) sRow[tid] = g_row_token[row0 + tid];
        __syncthreads();
    }

    int am = tid >> 2;
    int ak = (tid & 3) * 4;
    const float* arow = GATHER ? (Xin + (long)sRow[am]*KD)
                               : (Xin + (long)(row0 + am)*KD);
    int bk = tid >> 4;
    int bn = (tid & 15)*4;

    float c[4][4];
    #pragma unroll
    for (int i = 0; i < 4; i++)
        #pragma unroll
        for (int j = 0; j < 4; j++) c[i][j] = 0.f;

    const int KT = (KD + TKs - 1)/TKs;
    for (int kb = 0; kb < KT; kb++) {
        int k0 = kb*TKs;
        #pragma unroll
        for (int j = 0; j < 4; j++) {
            int k = k0 + ak + j;
            As[ak+j][am] = (k < KD) ? arow[k] : 0.f;
        }
        {
            int k = k0 + bk;
            bool kval = (k < KD);
            const float* brow = We + (long)k*ND + nb + bn;
            #pragma unroll
            for (int j = 0; j < 4; j++) {
                int n = nb + bn + j;
                Bs[bk][bn+j] = (kval && n < ND) ? brow[j] : 0.f;
            }
        }
        __syncthreads();
        #pragma unroll
        for (int kk = 0; kk < TKs; kk++) {
            float4 a = *(const float4*)&As[kk][ty*4];
            float4 b = *(const float4*)&Bs[kk][tx*4];
            float av[4] = {a.x,a.y,a.z,a.w};
            float bv[4] = {b.x,b.y,b.z,b.w};
            #pragma unroll
            for (int i = 0; i < 4; i++)
                #pragma unroll
                for (int j = 0; j < 4; j++) c[i][j] += av[i]*bv[j];
        }
        __syncthreads();
    }
    #pragma unroll
    for (int i = 0; i < 4; i++) {
        int r = row0 + ty*4 + i;
        #pragma unroll
        for (int j = 0; j < 4; j++) {
            int n = nb + tx*4 + j;
            if (n < ND) {
                float v = c[i][j] + be[n];
                if (RELU) v = fmaxf(v, 0.f);
                Y[(long)r*ND + n] = v;
            }
        }
    }
}

__global__ void combine_kernel(float* __restrict__ out) {
    int s = blockIdx.x;
    int d = threadIdx.x;
    int r0 = g_token_rows[2*s], r1 = g_token_rows[2*s+1];
    float g0 = g_gate[2*s], g1 = g_gate[2*s+1];
    out[(long)s*Ddim + d] = g0*g_A4[(long)r0*Ddim + d] + g1*g_A4[(long)r1*Ddim + d];
}

// ---------------------------------------------------------------------------
extern "C" void kernel_launch(void* const* d_in, const int* in_sizes, int n_in,
                              void* d_out, int out_size) {
    (void)in_sizes; (void)n_in; (void)out_size;
    const float* x     = (const float*)d_in[0];
    const float* noise = (const float*)d_in[1];
    const float* Wr    = (const float*)d_in[2];
    const float* W1    = (const float*)d_in[3];
    const float* b1    = (const float*)d_in[4];
    const float* W2    = (const float*)d_in[5];
    const float* b2    = (const float*)d_in[6];
    const float* W3    = (const float*)d_in[7];
    const float* b3    = (const float*)d_in[8];
    const float* W4    = (const float*)d_in[9];
    const float* b4    = (const float*)d_in[10];

    float* out       = (float*)d_out;
    float* out_final = out;
    float* out_sel   = out + (long)Stok*Ddim;
    float* out_loss  = out_sel + (long)Stok*Edim;

    void *pA1, *pA2, *pA3, *pA4;
    cudaGetSymbolAddress(&pA1, g_A1);
    cudaGetSymbolAddress(&pA2, g_A2);
    cudaGetSymbolAddress(&pA3, g_A3);
    cudaGetSymbolAddress(&pA4, g_A4);

    init_kernel<<<148, 256>>>();
    router_kernel<<<RBLOCKS, 256>>>(x, noise, Wr, out_sel);
    loss_kernel<<<1, 32>>>(out_loss);
    build_tiles_kernel<<<1, 1>>>();
    scatter_kernel<<<Stok/256, 256>>>();

    expert_gemm<Mdim, H1d, true,  true ><<<dim3(NT_MAX, (H1d+TN-1)/TN), 256>>>(x, W1, b1, (float*)pA1);
    expert_gemm<H1d,  H2d, true,  false><<<dim3(NT_MAX, (H2d+TN-1)/TN), 256>>>((const float*)pA1, W2, b2, (float*)pA2);
    expert_gemm<H2d,  H3d, true,  false><<<dim3(NT_MAX, (H3d+TN-1)/TN), 256>>>((const float*)pA2, W3, b3, (float*)pA3);
    expert_gemm<H3d,  Ddim,false, false><<<dim3(NT_MAX, (Ddim+TN-1)/TN), 256>>>((const float*)pA3, W4, b4, (float*)pA4);

    combine_kernel<<<Stok, Ddim>>>(out_final);
}

// round 5
// speedup vs baseline: 3.0861x; 3.0861x over previous
#include <cuda_runtime.h>
#include <cuda_bf16.h>
#include <cstdint>

// Problem constants
#define Stok 16384
#define Mdim 512
#define Edim 16
#define Ddim 256
#define H1d  500
#define H2d  500
#define H3d  1000

// Padded scratch strides
#define LD1 512
#define LD2 512
#define LD3 1024
#define LD4 256

// Tiling
#define TM 128                       // M rows per CTA tile (expert-padded)
#define NR (2*Stok + Edim*TM)        // 34816 padded assignment rows
#define NT_MAX (2*Stok/TM + Edim)    // 272 tiles max
#define RBLOCKS (Stok/8)             // 2048 router blocks

// -------- scratch (device globals; allocation-free per harness rules) --------
__device__ float g_A1[(size_t)NR*LD1];
__device__ float g_A2[(size_t)NR*LD2];
__device__ float g_A3[(size_t)NR*LD3];
__device__ float g_A4[(size_t)NR*LD4];
__device__ int   g_row_token[NR];
__device__ int   g_token_rows[2*Stok];
__device__ float g_gate[2*Stok];
__device__ int   g_topk[2*Stok];
__device__ int   g_counts[Edim];
__device__ int   g_cursor[Edim];
__device__ int   g_offsets[Edim];
__device__ int   g_tile_expert[NT_MAX];
__device__ int   g_tile_row0[NT_MAX];
__device__ int   g_n_tiles;
__device__ float g_proxy_partial[RBLOCKS*Edim];

// ---------------------------------------------------------------------------
__device__ __forceinline__ void split2(float a, float b, uint32_t& hi, uint32_t& lo) {
    __nv_bfloat16 ha = __float2bfloat16(a), hb = __float2bfloat16(b);
    float ra = a - __bfloat162float(ha);
    float rb = b - __bfloat162float(hb);
    __nv_bfloat162 H = __halves2bfloat162(ha, hb);
    __nv_bfloat162 L = __floats2bfloat162_rn(ra, rb);
    hi = *(uint32_t*)&H; lo = *(uint32_t*)&L;
}

#define MMA4(d, a, b) \
    asm volatile("mma.sync.aligned.m16n8k16.row.col.f32.bf16.bf16.f32 " \
        "{%0,%1,%2,%3},{%4,%5,%6,%7},{%8,%9},{%0,%1,%2,%3};" \
        : "+f"((d)[0]), "+f"((d)[1]), "+f"((d)[2]), "+f"((d)[3]) \
        : "r"((a)[0]), "r"((a)[1]), "r"((a)[2]), "r"((a)[3]), "r"((b)[0]), "r"((b)[1]))

// ---------------------------------------------------------------------------
__global__ void init_kernel() {
    int t = blockIdx.x*blockDim.x + threadIdx.x;
    if (t < Edim) { g_counts[t] = 0; g_cursor[t] = 0; }
    for (int r = t; r < NR; r += gridDim.x*blockDim.x) g_row_token[r] = 0;
}

__global__ void router_kernel(const float* __restrict__ x,
                              const float* __restrict__ noise,
                              const float* __restrict__ Wr,
                              float* __restrict__ out_sel) {
    __shared__ float sWr[Edim*Mdim];
    __shared__ float sP[8][Edim];
    int tid = threadIdx.x;
    for (int i = tid; i < Edim*Mdim; i += 256) sWr[i] = Wr[i];
    __syncthreads();

    int warp = tid >> 5, lane = tid & 31;
    int s = blockIdx.x*8 + warp;

    float p[Edim];
    #pragma unroll
    for (int e = 0; e < Edim; e++) p[e] = 0.f;
    const float* xr = x + (size_t)s*Mdim;
    for (int k = lane; k < Mdim; k += 32) {
        float xv = xr[k];
        #pragma unroll
        for (int e = 0; e < Edim; e++) p[e] += xv * sWr[e*Mdim + k];
    }
    #pragma unroll
    for (int e = 0; e < Edim; e++) {
        #pragma unroll
        for (int o = 16; o > 0; o >>= 1) p[e] += __shfl_xor_sync(0xffffffffu, p[e], o);
    }
    float mx = -1e30f;
    #pragma unroll
    for (int e = 0; e < Edim; e++) { p[e] += noise[(size_t)s*Edim + e]; mx = fmaxf(mx, p[e]); }
    float sum = 0.f;
    #pragma unroll
    for (int e = 0; e < Edim; e++) { p[e] = __expf(p[e]-mx); sum += p[e]; }
    float inv = 1.f/sum;
    #pragma unroll
    for (int e = 0; e < Edim; e++) p[e] *= inv;

    int e0 = 0; float v0 = p[0];
    #pragma unroll
    for (int e = 1; e < Edim; e++) if (p[e] > v0) { v0 = p[e]; e0 = e; }
    int e1 = -1; float v1 = -1.f;
    #pragma unroll
    for (int e = 0; e < Edim; e++) if (e != e0 && p[e] > v1) { v1 = p[e]; e1 = e; }
    float gs = v0 + v1;

    if (lane == 0) {
        g_topk[2*s]   = e0; g_topk[2*s+1] = e1;
        g_gate[2*s]   = v0/gs; g_gate[2*s+1] = v1/gs;
        atomicAdd(&g_counts[e0], 1);
        atomicAdd(&g_counts[e1], 1);
        #pragma unroll
        for (int e = 0; e < Edim; e++) sP[warp][e] = p[e];
    }
    if (lane < Edim)
        out_sel[(size_t)s*Edim + lane] = (lane == e0 || lane == e1) ? 1.f : 0.f;
    __syncthreads();
    if (tid < Edim) {
        float acc = 0.f;
        #pragma unroll
        for (int w = 0; w < 8; w++) acc += sP[w][tid];
        g_proxy_partial[(size_t)blockIdx.x*Edim + tid] = acc;
    }
}

__global__ void loss_kernel(float* __restrict__ out_loss) {
    __shared__ float sp[Edim];
    int e = threadIdx.x;
    if (e < Edim) {
        float acc = 0.f;
        for (int b = 0; b < RBLOCKS; b++) acc += g_proxy_partial[(size_t)b*Edim + e];
        sp[e] = acc;
    }
    __syncthreads();
    if (e == 0) {
        float l = 0.f;
        for (int i = 0; i < Edim; i++) l += sp[i] * (float)g_counts[i];
        out_loss[0] = l * (float)Edim / ((float)Stok * (float)Stok);
        out_loss[1] = 0.f;
    }
}

__global__ void build_tiles_kernel() {
    int off = 0, nt = 0;
    for (int e = 0; e < Edim; e++) {
        g_offsets[e] = off;
        int c = g_counts[e];
        int ct = (c + TM - 1)/TM;
        for (int t = 0; t < ct; t++) { g_tile_expert[nt] = e; g_tile_row0[nt] = off + t*TM; nt++; }
        off += ct*TM;
    }
    g_n_tiles = nt;
}

__global__ void scatter_kernel() {
    int s = blockIdx.x*blockDim.x + threadIdx.x;
    if (s >= Stok) return;
    #pragma unroll
    for (int k = 0; k < 2; k++) {
        int e = g_topk[2*s+k];
        int pos = atomicAdd(&g_cursor[e], 1);
        int r = g_offsets[e] + pos;
        g_row_token[r] = s;
        g_token_rows[2*s+k] = r;
    }
}

// ---------------------------------------------------------------------------
// HMMA grouped GEMM: Y[r, 0:ND] = act( X[r,:] @ W[e] + b[e] )
// CTA 128x128, 256 threads, warp tile 64x32. K-chunk = 32 bf16 (split hi/lo,
// 3 mma terms). Smem rows = 32 halves (64B = 4 groups of 16B), XOR-swizzled
// by ((row>>1)&3) -> conflict-free STS.128 stores and LDS.32 frag loads.
// Per buffer: A_hi 8K | A_lo 8K | B_hi 8K | B_lo 8K = 32KB; x2 buffers = 64KB.
#define GBUF 32768
#define SMEM_MM (2*GBUF)

template<int KD, int ND, int LDS_, int LDD_, bool RELU, bool GATHER>
__global__ void __launch_bounds__(256, 2)
expert_gemm_mma(const float* __restrict__ Xin, const float* __restrict__ W,
                const float* __restrict__ Bias, float* __restrict__ Y) {
    int tile = blockIdx.x;
    if (tile >= g_n_tiles) return;
    int row0 = g_tile_row0[tile];
    int e    = g_tile_expert[tile];
    int nb   = blockIdx.y * 128;
    const float* We = W + (size_t)e*KD*ND;
    const float* be = Bias + (size_t)e*ND;

    extern __shared__ char smem[];
    int tid = threadIdx.x, wid = tid >> 5, lane = tid & 31;
    int g = lane >> 2, tig = lane & 3;
    int m0 = (wid & 1) * 64, n0 = (wid >> 1) * 32;

    // ---- producer assignments ----
    // A: thread -> row am = tid>>1, k-half akh = (tid&1)*16 (16 halves = groups g0,g0+1)
    int am = tid >> 1, akh = (tid & 1) * 16;
    int ag0 = (tid & 1) * 2;
    int asw = (am >> 1) & 3;
    const float* arow;
    if (GATHER) arow = Xin + (size_t)g_row_token[row0 + am]*LDS_;
    else        arow = Xin + (size_t)(row0 + am)*LDS_;
    // B: thread -> n-row bn = tid&127, k-group bkg = tid>>7 (16 halves)
    int bn = tid & 127, bkg = tid >> 7;
    int bg0 = bkg * 2;
    int bsw = (bn >> 1) & 3;
    bool colok = (nb + bn) < ND;
    const float* wcol = We + nb + bn;

    const int NCH = (KD + 31) / 32;

    float acc[4][4][4];
    #pragma unroll
    for (int i = 0; i < 4; i++)
        #pragma unroll
        for (int j = 0; j < 4; j++)
            #pragma unroll
            for (int c = 0; c < 4; c++) acc[i][j][c] = 0.f;

    uint4 sAh0, sAh1, sAl0, sAl1, sBh0, sBh1, sBl0, sBl1;

    // load+convert chunk into regs
    auto load_chunk = [&](int ch) {
        int k0 = ch * 32;
        // A
        {
            float v[16];
            int kb = k0 + akh;
            if (kb + 15 < KD) {
                #pragma unroll
                for (int q = 0; q < 4; q++) {
                    float4 f = *(const float4*)(arow + kb + q*4);
                    v[q*4+0]=f.x; v[q*4+1]=f.y; v[q*4+2]=f.z; v[q*4+3]=f.w;
                }
            } else {
                #pragma unroll
                for (int i = 0; i < 16; i++) v[i] = (kb + i < KD) ? arow[kb + i] : 0.f;
            }
            uint32_t h[8], l[8];
            #pragma unroll
            for (int i = 0; i < 8; i++) split2(v[2*i], v[2*i+1], h[i], l[i]);
            sAh0 = make_uint4(h[0],h[1],h[2],h[3]); sAh1 = make_uint4(h[4],h[5],h[6],h[7]);
            sAl0 = make_uint4(l[0],l[1],l[2],l[3]); sAl1 = make_uint4(l[4],l[5],l[6],l[7]);
        }
        // B (transpose W[k][n] -> rows of n)
        {
            float v[16];
            int kb = k0 + bkg*16;
            #pragma unroll
            for (int i = 0; i < 16; i++) {
                int k = kb + i;
                v[i] = (colok && k < KD) ? wcol[(size_t)k*ND] : 0.f;
            }
            uint32_t h[8], l[8];
            #pragma unroll
            for (int i = 0; i < 8; i++) split2(v[2*i], v[2*i+1], h[i], l[i]);
            sBh0 = make_uint4(h[0],h[1],h[2],h[3]); sBh1 = make_uint4(h[4],h[5],h[6],h[7]);
            sBl0 = make_uint4(l[0],l[1],l[2],l[3]); sBl1 = make_uint4(l[4],l[5],l[6],l[7]);
        }
    };

    auto store_chunk = [&](int b) {
        char* buf = smem + b*GBUF;
        char* Ah = buf;        char* Al = buf + 8192;
        char* Bh = buf + 16384; char* Bl = buf + 24576;
        *(uint4*)(Ah + am*64 + (((ag0  ) ^ asw) << 4)) = sAh0;
        *(uint4*)(Ah + am*64 + (((ag0+1) ^ asw) << 4)) = sAh1;
        *(uint4*)(Al + am*64 + (((ag0  ) ^ asw) << 4)) = sAl0;
        *(uint4*)(Al + am*64 + (((ag0+1) ^ asw) << 4)) = sAl1;
        *(uint4*)(Bh + bn*64 + (((bg0  ) ^ bsw) << 4)) = sBh0;
        *(uint4*)(Bh + bn*64 + (((bg0+1) ^ bsw) << 4)) = sBh1;
        *(uint4*)(Bl + bn*64 + (((bg0  ) ^ bsw) << 4)) = sBl0;
        *(uint4*)(Bl + bn*64 + (((bg0+1) ^ bsw) << 4)) = sBl1;
    };

    auto compute = [&](int b) {
        const char* buf = smem + b*GBUF;
        const char* Ah = buf;         const char* Al = buf + 8192;
        const char* Bh = buf + 16384; const char* Bl = buf + 24576;
        #pragma unroll
        for (int ks = 0; ks < 2; ks++) {
            uint32_t bh[4][2], bl[4][2];
            #pragma unroll
            for (int nf = 0; nf < 4; nf++) {
                int row = n0 + 8*nf + g;
                int rb  = row*64 + tig*4;
                int sw  = (row >> 1) & 3;
                int o0 = rb + (((2*ks  ) ^ sw) << 4);
                int o1 = rb + (((2*ks+1) ^ sw) << 4);
                bh[nf][0] = *(const uint32_t*)(Bh + o0);
                bh[nf][1] = *(const uint32_t*)(Bh + o1);
                bl[nf][0] = *(const uint32_t*)(Bl + o0);
                bl[nf][1] = *(const uint32_t*)(Bl + o1);
            }
            #pragma unroll
            for (int mf = 0; mf < 4; mf++) {
                int r0w = m0 + 16*mf + g, r1w = r0w + 8;
                int rb0 = r0w*64 + tig*4, rb1 = r1w*64 + tig*4;
                int s0 = (r0w >> 1) & 3,  s1 = (r1w >> 1) & 3;
                int o00 = rb0 + (((2*ks  ) ^ s0) << 4);
                int o10 = rb1 + (((2*ks  ) ^ s1) << 4);
                int o01 = rb0 + (((2*ks+1) ^ s0) << 4);
                int o11 = rb1 + (((2*ks+1) ^ s1) << 4);
                uint32_t ah[4], al[4];
                ah[0] = *(const uint32_t*)(Ah + o00);
                ah[1] = *(const uint32_t*)(Ah + o10);
                ah[2] = *(const uint32_t*)(Ah + o01);
                ah[3] = *(const uint32_t*)(Ah + o11);
                al[0] = *(const uint32_t*)(Al + o00);
                al[1] = *(const uint32_t*)(Al + o10);
                al[2] = *(const uint32_t*)(Al + o01);
                al[3] = *(const uint32_t*)(Al + o11);
                #pragma unroll
                for (int nf = 0; nf < 4; nf++) {
                    MMA4(acc[mf][nf], ah, bh[nf]);
                    MMA4(acc[mf][nf], ah, bl[nf]);
                    MMA4(acc[mf][nf], al, bh[nf]);
                }
            }
        }
    };

    load_chunk(0);
    store_chunk(0);
    __syncthreads();
    for (int ch = 0; ch < NCH; ch++) {
        if (ch + 1 < NCH) load_chunk(ch + 1);
        compute(ch & 1);
        if (ch + 1 < NCH) store_chunk((ch + 1) & 1);
        __syncthreads();
    }

    // epilogue: write 64x32 warp tile
    #pragma unroll
    for (int mf = 0; mf < 4; mf++) {
        int r0 = row0 + m0 + 16*mf + g;
        #pragma unroll
        for (int nf = 0; nf < 4; nf++) {
            int cc = nb + n0 + 8*nf + 2*tig;
            if (cc < ND) {
                float b0 = be[cc], b1 = be[cc+1];
                float v0 = acc[mf][nf][0] + b0;
                float v1 = acc[mf][nf][1] + b1;
                float v2 = acc[mf][nf][2] + b0;
                float v3 = acc[mf][nf][3] + b1;
                if (RELU) {
                    v0 = fmaxf(v0, 0.f); v1 = fmaxf(v1, 0.f);
                    v2 = fmaxf(v2, 0.f); v3 = fmaxf(v3, 0.f);
                }
                *(float2*)(Y + (size_t)r0*LDD_ + cc)     = make_float2(v0, v1);
                *(float2*)(Y + (size_t)(r0+8)*LDD_ + cc) = make_float2(v2, v3);
            }
        }
    }
}

__global__ void combine_kernel(float* __restrict__ out) {
    int s = blockIdx.x;
    int d = threadIdx.x;
    int r0 = g_token_rows[2*s], r1 = g_token_rows[2*s+1];
    float g0 = g_gate[2*s], g1 = g_gate[2*s+1];
    out[(size_t)s*Ddim + d] = g0*g_A4[(size_t)r0*LD4 + d] + g1*g_A4[(size_t)r1*LD4 + d];
}

// ---------------------------------------------------------------------------
extern "C" void kernel_launch(void* const* d_in, const int* in_sizes, int n_in,
                              void* d_out, int out_size) {
    (void)in_sizes; (void)n_in; (void)out_size;
    const float* x     = (const float*)d_in[0];
    const float* noise = (const float*)d_in[1];
    const float* Wr    = (const float*)d_in[2];
    const float* W1    = (const float*)d_in[3];
    const float* b1    = (const float*)d_in[4];
    const float* W2    = (const float*)d_in[5];
    const float* b2    = (const float*)d_in[6];
    const float* W3    = (const float*)d_in[7];
    const float* b3    = (const float*)d_in[8];
    const float* W4    = (const float*)d_in[9];
    const float* b4    = (const float*)d_in[10];

    float* out       = (float*)d_out;
    float* out_final = out;
    float* out_sel   = out + (size_t)Stok*Ddim;
    float* out_loss  = out_sel + (size_t)Stok*Edim;

    void *pA1, *pA2, *pA3, *pA4;
    cudaGetSymbolAddress(&pA1, g_A1);
    cudaGetSymbolAddress(&pA2, g_A2);
    cudaGetSymbolAddress(&pA3, g_A3);
    cudaGetSymbolAddress(&pA4, g_A4);

    cudaFuncSetAttribute(expert_gemm_mma<Mdim, H1d, Mdim, LD1, true,  true >, cudaFuncAttributeMaxDynamicSharedMemorySize, SMEM_MM);
    cudaFuncSetAttribute(expert_gemm_mma<H1d,  H2d, LD1,  LD2, true,  false>, cudaFuncAttributeMaxDynamicSharedMemorySize, SMEM_MM);
    cudaFuncSetAttribute(expert_gemm_mma<H2d,  H3d, LD2,  LD3, true,  false>, cudaFuncAttributeMaxDynamicSharedMemorySize, SMEM_MM);
    cudaFuncSetAttribute(expert_gemm_mma<H3d,  Ddim,LD3,  LD4, false, false>, cudaFuncAttributeMaxDynamicSharedMemorySize, SMEM_MM);

    init_kernel<<<148, 256>>>();
    router_kernel<<<RBLOCKS, 256>>>(x, noise, Wr, out_sel);
    loss_kernel<<<1, 32>>>(out_loss);
    build_tiles_kernel<<<1, 1>>>();
    scatter_kernel<<<Stok/256, 256>>>();

    expert_gemm_mma<Mdim, H1d, Mdim, LD1, true,  true ><<<dim3(NT_MAX, 4), 256, SMEM_MM>>>(x, W1, b1, (float*)pA1);
    expert_gemm_mma<H1d,  H2d, LD1,  LD2, true,  false><<<dim3(NT_MAX, 4), 256, SMEM_MM>>>((const float*)pA1, W2, b2, (float*)pA2);
    expert_gemm_mma<H2d,  H3d, LD2,  LD3, true,  false><<<dim3(NT_MAX, 8), 256, SMEM_MM>>>((const float*)pA2, W3, b3, (float*)pA3);
    expert_gemm_mma<H3d,  Ddim,LD3,  LD4, false, false><<<dim3(NT_MAX, 2), 256, SMEM_MM>>>((const float*)pA3, W4, b4, (float*)pA4);

    combine_kernel<<<Stok, Ddim>>>(out_final);
}